// round 5
// baseline (speedup 1.0000x reference)
#include <cuda_runtime.h>

#define E    4096
#define NVAR 1024
#define NCHK 512
#define EPS32 1.1920929e-07f

// Upper-triangle peers of each edge (columns > row), ascending. Only rows with
// g_ucnt==7 (check representatives) have complete lists -- and those are the
// only ones decode ever reads.
__device__ int g_up[E * 7];
__device__ __align__(16) int g_ucnt[E];

// ---------------- kernel A: upper-triangle peer scan (no atomics) -----------
// w_odd_to_even is symmetric, zero diagonal, 7 nonzeros per row. Each warp
// handles rows gw and 4095-gw (combined upper-triangle length ~= one full row,
// perfect balance). float4 loads + warp-ballot compaction emit peers ascending.
// Early-exit once 7 peers found (base is warp-uniform).
__global__ void build_peers_kernel(const float4* __restrict__ w) {
    int gw   = (blockIdx.x * blockDim.x + threadIdx.x) >> 5;   // 0..2047
    int lane = threadIdx.x & 31;
#pragma unroll
    for (int pass = 0; pass < 2; pass++) {
        int row = pass ? (E - 1 - gw) : gw;
        const float4* r = w + (size_t)row * (E / 4);
        int* dst = g_up + row * 7;
        int f0 = (row + 1) >> 2;              // first float4 with any col > row
        int iters = ((E / 4) - f0 + 31) >> 5;
        int base = 0;
        for (int i = 0; i < iters; i++) {
            int f = f0 + i * 32 + lane;
            float4 v = (f < E / 4) ? r[f] : make_float4(0.f, 0.f, 0.f, 0.f);
            int col = f * 4;
            int c0 = (v.x != 0.0f) & (col     > row);
            int c1 = (v.y != 0.0f) & (col + 1 > row);
            int c2 = (v.z != 0.0f) & (col + 2 > row);
            int c3 = (v.w != 0.0f) & (col + 3 > row);
            int cnt = c0 + c1 + 2 * (c2 + c3) - c2 - c3 + c2 + c3; // = c0+c1+c2+c3
            cnt = c0 + c1 + c2 + c3;
            unsigned b0 = __ballot_sync(0xffffffffu, cnt & 1);
            unsigned b1 = __ballot_sync(0xffffffffu, cnt & 2);
            unsigned b2 = __ballot_sync(0xffffffffu, cnt & 4);
            if (b0 | b1 | b2) {
                unsigned mlt = (1u << lane) - 1u;
                int prior = base + __popc(b0 & mlt) + 2 * __popc(b1 & mlt)
                                 + 4 * __popc(b2 & mlt);
                if (c0) dst[prior++] = col;
                if (c1) dst[prior++] = col + 1;
                if (c2) dst[prior++] = col + 2;
                if (c3) dst[prior++] = col + 3;
                base += __popc(b0) + 2 * __popc(b1) + 4 * __popc(b2);
                if (base >= 7) break;          // warp-uniform (base from ballots)
            }
        }
        if (lane == 0) g_ucnt[row] = base;
    }
}

// ---------------- math helpers ----------------------------------------------
__device__ __forceinline__ float tanh_acc(float a) {
    return 1.0f - __fdividef(2.0f, __expf(2.0f * a) + 1.0f);   // inf-safe
}

__device__ __forceinline__ float atanh2(float v) {
    // reference clamps: v>=1 -> 1-eps, v<=-1 -> -1+eps (exact copy)
    v = (v >= 1.0f) ? (1.0f - EPS32) : v;
    v = (v <= -1.0f) ? (-1.0f + EPS32) : v;
    return __logf(__fdividef(1.0f + v, 1.0f - v));   // 2*atanh(v)
}

__device__ __forceinline__ float zsub(float o) {
    return (o == 0.0f) ? 1.0f : o;   // reference maps exact zeros -> identity
}

// ---------------- kernel B: full decode, one persistent block ----------------
__global__ __launch_bounds__(1024, 1)
void decode_kernel(const float* __restrict__ x, float* __restrict__ out) {
    __shared__ float sh_odd[E];      // odd messages, natural edge order
    __shared__ float sh_even[E];     // even messages, natural edge order
    __shared__ int   chk_list[NCHK]; // representative (min) edge per check
    __shared__ int   chk_ctr;

    const int t = threadIdx.x;
    const float llr = x[t];

    if (t == 0) chk_ctr = 0;
    ((float4*)sh_even)[t] = make_float4(0.f, 0.f, 0.f, 0.f);
    __syncthreads();

    // claim checks: edge e is representative iff all 7 peers are above it
    int4 uc = ((const int4*)g_ucnt)[t];
    if (uc.x == 7) chk_list[atomicAdd(&chk_ctr, 1)] = 4 * t;
    if (uc.y == 7) chk_list[atomicAdd(&chk_ctr, 1)] = 4 * t + 1;
    if (uc.z == 7) chk_list[atomicAdd(&chk_ctr, 1)] = 4 * t + 2;
    if (uc.w == 7) chk_list[atomicAdd(&chk_ctr, 1)] = 4 * t + 3;
    __syncthreads();

    // check owners cache their sorted 8-edge list in registers (rep = minimum)
    int id0 = 0, id1 = 0, id2 = 0, id3 = 0, id4 = 0, id5 = 0, id6 = 0, id7 = 0;
    if (t < NCHK) {
        int rep = chk_list[t];
        const int* p = g_up + rep * 7;
        id0 = rep;
        id1 = p[0]; id2 = p[1]; id3 = p[2]; id4 = p[3];
        id5 = p[4]; id6 = p[5]; id7 = p[6];
    }

    // ---- 5 BP iterations -----------------------------------------------------
#pragma unroll 1
    for (int it = 0; it < 5; it++) {
        // odd stage: vectorized, natural order (thread t = variable t)
        float4 ev = ((float4*)sh_even)[t];
        float vs = ev.x + ev.y + ev.z + ev.w;
        float4 od;
        od.x = tanh_acc(0.5f * (llr + vs - ev.x));
        od.y = tanh_acc(0.5f * (llr + vs - ev.y));
        od.z = tanh_acc(0.5f * (llr + vs - ev.z));
        od.w = tanh_acc(0.5f * (llr + vs - ev.w));
        ((float4*)sh_odd)[t] = od;
        __syncthreads();

        // even stage: 512 check owners gather 8, extrinsic products, scatter 8
        if (t < NCHK) {
            float a0 = zsub(sh_odd[id0]), a1 = zsub(sh_odd[id1]);
            float a2 = zsub(sh_odd[id2]), a3 = zsub(sh_odd[id3]);
            float a4 = zsub(sh_odd[id4]), a5 = zsub(sh_odd[id5]);
            float a6 = zsub(sh_odd[id6]), a7 = zsub(sh_odd[id7]);
            float p01 = a0 * a1, p23 = a2 * a3, p45 = a4 * a5, p67 = a6 * a7;
            float q03 = p01 * p23, q47 = p45 * p67;
            sh_even[id0] = atanh2(a1 * p23 * q47);
            sh_even[id1] = atanh2(a0 * p23 * q47);
            sh_even[id2] = atanh2(p01 * a3 * q47);
            sh_even[id3] = atanh2(p01 * a2 * q47);
            sh_even[id4] = atanh2(q03 * a5 * p67);
            sh_even[id5] = atanh2(q03 * a4 * p67);
            sh_even[id6] = atanh2(q03 * p45 * a7);
            sh_even[id7] = atanh2(q03 * p45 * a6);
        }
        __syncthreads();
    }

    // ---- epilogue: out[n] = sigmoid(x[n] + sum of even over var n) -----------
    float4 ev = ((float4*)sh_even)[t];
    float z = llr + ev.x + ev.y + ev.z + ev.w;
    out[t] = __fdividef(1.0f, 1.0f + __expf(-z));
}

// ---------------- launch -----------------------------------------------------
extern "C" void kernel_launch(void* const* d_in, const int* in_sizes, int n_in,
                              void* d_out, int out_size) {
    (void)in_sizes; (void)n_in; (void)out_size;
    const float*  x = (const float*)d_in[0];
    const float4* w = (const float4*)d_in[2];   // w_odd_to_even [E,E]
    float* out = (float*)d_out;

    build_peers_kernel<<<256, 256>>>(w);   // 2048 warps, paired rows
    decode_kernel<<<1, 1024>>>(x, out);
}